// round 16
// baseline (speedup 1.0000x reference)
#include <cuda_runtime.h>
#include <cuda_fp16.h>
#include <cstdint>

// GRU seq2seq forecaster — fused tensor-core recurrence, 2 CTAs/SM anti-phase,
// Whh-lo fragments in SMEM (spill fix for the 128-reg cap).
//  K0: xsplit — x -> fp16 PERMUTED 64B records (frag-major u32 layout).
//  K1: CTA = 16 rows, 256 thr, 8 warps; warp wn owns 8 units x 3 gates.
//      Grid 256 -> 2 CTAs/SM slide anti-phase. Whh hi in regs, lo via LDS.64.
//  (Identical to R14 submission — prior bench failed on infrastructure.)

#define B_    4096
#define TIN   168
#define C_    32
#define H_    64
#define TOUT  24

typedef uint32_t u32;
typedef unsigned long long u64;

__device__ u32 g_xs[(size_t)TIN * B_ * 16];   // 44 MB fp16 permuted x records

__device__ __forceinline__ float tanhap(float a) {
    float r; asm("tanh.approx.f32 %0, %1;" : "=f"(r) : "f"(a)); return r;
}
__device__ __forceinline__ float fsig(float a) {           // sigma(a)=0.5+0.5*tanh(a/2)
    return fmaf(tanhap(0.5f * a), 0.5f, 0.5f);
}
__device__ __forceinline__ u32 packh2(float a, float b) {  // low fp16 = a, high = b
    u32 d; asm("cvt.rn.f16x2.f32 %0, %1, %2;" : "=r"(d) : "f"(b), "f"(a)); return d;
}
__device__ __forceinline__ void splith2(float a, float b, u32& hi2, u32& lo2) {
    hi2 = packh2(a, b);
    __half2 hv = *reinterpret_cast<const __half2*>(&hi2);
    lo2 = packh2(a - __low2float(hv), b - __high2float(hv));
}
__device__ __forceinline__ void MMA(float acc[4], u32 a0, u32 a1, u32 a2, u32 a3,
                                    u32 b0, u32 b1) {
    asm volatile(
        "mma.sync.aligned.m16n8k16.row.col.f32.f16.f16.f32 "
        "{%0,%1,%2,%3}, {%4,%5,%6,%7}, {%8,%9}, {%0,%1,%2,%3};"
        : "+f"(acc[0]), "+f"(acc[1]), "+f"(acc[2]), "+f"(acc[3])
        : "r"(a0), "r"(a1), "r"(a2), "r"(a3), "r"(b0), "r"(b1));
}
__device__ __forceinline__ u32 smem_u32(const void* p) {
    u32 a;
    asm("{ .reg .u64 t; cvta.to.shared.u64 t, %1; cvt.u32.u64 %0, t; }" : "=r"(a) : "l"(p));
    return a;
}
__device__ __forceinline__ void cp16(u32 daddr, const void* gsrc) {
    asm volatile("cp.async.cg.shared.global [%0], [%1], 16;"
                 :: "r"(daddr), "l"(gsrc) : "memory");
}

// ============================ kernel 0: x pre-split (fp16, permuted) ============================
__global__ __launch_bounds__(256)
void xsplit_kernel(const float* __restrict__ x)
{
    const int p = blockIdx.x * 256 + threadIdx.x;      // t*B + b
    const int t = p >> 12, b = p & (B_ - 1);
    const float4* s4 = reinterpret_cast<const float4*>(x + ((size_t)b * TIN + t) * C_);
    float4 v[8];
#pragma unroll
    for (int i = 0; i < 8; i++) v[i] = s4[i];
    u32 s[16];
#pragma unroll
    for (int i = 0; i < 8; i++) {
        s[2 * i]     = packh2(v[i].x, v[i].y);
        s[2 * i + 1] = packh2(v[i].z, v[i].w);
    }
    uint4* dst = reinterpret_cast<uint4*>(g_xs + (size_t)p * 16);
#pragma unroll
    for (int j4 = 0; j4 < 4; j4++)
        dst[j4] = make_uint4(s[j4], s[4 + j4], s[8 + j4], s[12 + j4]);
}

// ============================ kernel 1: fused recurrence ============================
#define HSu 36     // sH row stride (u32): 32 data + 4 pad
#define PSu 16
#define XSu 16

#define OFF_H   0                         // [2 par][16][HSu] u32 = 4608
#define OFF_P   4608                      // [2 par][16][PSu] u32 = 2048
#define OFF_X   6656                      // [2 buf][16][XSu] u32 = 2048
#define OFF_WF  8704                      // [8 wn][3 nt][2 ks][32] uint2 = 12288
#define OFF_PF  20992                     // [4][4 ks][32] uint4 = 8192
#define OFF_WL  29184                     // [8 wn][3 nt][4 ks][32] uint2 = 24576
#define SM_TOTAL 53760

#define AFRAG_FROM(v0a, v0b, v1a, v1b, a0, a1, a2, a3)                     \
    a0[0]=(v0a).x; a2[0]=(v0a).y; a1[0]=(v1a).x; a3[0]=(v1a).y;            \
    a0[1]=(v0a).z; a2[1]=(v0a).w; a1[1]=(v1a).z; a3[1]=(v1a).w;            \
    a0[2]=(v0b).x; a2[2]=(v0b).y; a1[2]=(v1b).x; a3[2]=(v1b).y;            \
    a0[3]=(v0b).z; a2[3]=(v0b).w; a1[3]=(v1b).z; a3[3]=(v1b).w;

__global__ __launch_bounds__(256, 2)
void gru_fused(const float* __restrict__ x,
               const float* __restrict__ eWih, const float* __restrict__ eWhh,
               const float* __restrict__ eBih, const float* __restrict__ eBhh,
               const float* __restrict__ dWih, const float* __restrict__ dWhh,
               const float* __restrict__ dBih, const float* __restrict__ dBhh,
               const float* __restrict__ pW,   const float* __restrict__ pB,
               float* __restrict__ out)
{
    extern __shared__ __align__(16) char smem[];
    u32* sHu       = reinterpret_cast<u32*>(smem + OFF_H);
    u32* sPu       = reinterpret_cast<u32*>(smem + OFF_P);
    const u32* sXu = reinterpret_cast<const u32*>(smem + OFF_X);
    uint2* sWf     = reinterpret_cast<uint2*>(smem + OFF_WF);
    uint4* sPf     = reinterpret_cast<uint4*>(smem + OFF_PF);
    uint2* sWl     = reinterpret_cast<uint2*>(smem + OFF_WL);
    const u32 smb = smem_u32(smem);

    const int tid  = threadIdx.x;
    const int wn   = tid >> 5;         // unit octet 0..7 (r,z,n of 8 units)
    const int lane = tid & 31;
    const int g  = lane >> 2;
    const int tg = lane & 3;
    const int R0 = g, R1 = g + 8;      // 16-row tile
    const int rowbase = blockIdx.x * 16;

    for (int i = tid; i < 2 * 16 * HSu; i += 256) sHu[i] = 0;

    // ---- stage encoder Wih frags (hi fp16 only), each warp its wn ----
#pragma unroll
    for (int nt = 0; nt < 3; nt++)
#pragma unroll
        for (int ks = 0; ks < 2; ks++) {
            const float* wr = eWih + (nt * 64 + 8 * wn + g) * 32 + ks * 16 + 2 * tg;
            sWf[((wn * 3 + nt) * 2 + ks) * 32 + lane] =
                make_uint2(packh2(wr[0], wr[1]), packh2(wr[8], wr[9]));
        }
    // ---- encoder Whh frags: hi fp16 in registers (24 u32), lo -> SMEM ----
    u32 bh[3][4][2];
#pragma unroll
    for (int nt = 0; nt < 3; nt++) {
        const float* row = eWhh + (nt * 64 + 8 * wn + g) * 64;
#pragma unroll
        for (int ks = 0; ks < 4; ks++) {
            const int k0 = ks * 16 + 2 * tg;
            u32 h0, l0, h1, l1;
            splith2(row[k0],     row[k0 + 1], h0, l0);
            splith2(row[k0 + 8], row[k0 + 9], h1, l1);
            bh[nt][ks][0] = h0; bh[nt][ks][1] = h1;
            sWl[((wn * 3 + nt) * 4 + ks) * 32 + lane] = make_uint2(l0, l1);
        }
    }
    float ebr[2], ebz[2], eni[2], enh[2];
#pragma unroll
    for (int c = 0; c < 2; c++) {
        const int u = 8 * wn + 2 * tg + c;
        ebr[c] = eBih[u] + eBhh[u];
        ebz[c] = eBih[64 + u] + eBhh[64 + u];
        eni[c] = eBih[128 + u];
        enh[c] = eBhh[128 + u];
    }
    __syncthreads();

    if (tid < 64) {   // prologue: prefetch x tile t=0 (16 rows x 64B)
        const int row = tid >> 2, ch = tid & 3;
        const char* src = reinterpret_cast<const char*>(
            g_xs + ((size_t)(rowbase + row)) * 16) + ch * 16;
        cp16(smb + OFF_X + row * 64 + ch * 16, src);
        asm volatile("cp.async.commit_group;" ::: "memory");
    }

    float h[4];
#pragma unroll
    for (int e = 0; e < 4; e++) h[e] = 0.0f;
    int hp = 0;

    // ======================= encoder: 168 steps =======================
    for (int t = 0; t < TIN; t++) {
        asm volatile("cp.async.wait_group 0;" ::: "memory");
        __syncthreads();
        if (t + 1 < TIN && tid < 64) {
            const int row = tid >> 2, ch = tid & 3;
            const char* src = reinterpret_cast<const char*>(
                g_xs + ((size_t)(t + 1) * B_ + rowbase + row) * 16) + ch * 16;
            cp16(smb + OFF_X + ((t + 1) & 1) * 1024 + row * 64 + ch * 16, src);
            asm volatile("cp.async.commit_group;" ::: "memory");
        }

        const u32* hbu = sHu + hp * (16 * HSu);
        const uint4* h0p = reinterpret_cast<const uint4*>(hbu + R0 * HSu + tg * 8);
        const uint4* h1p = reinterpret_cast<const uint4*>(hbu + R1 * HSu + tg * 8);
        const uint4 v0a = h0p[0], v0b = h0p[1], v1a = h1p[0], v1b = h1p[1];
        u32 a0[4], a1[4], a2[4], a3[4];
        AFRAG_FROM(v0a, v0b, v1a, v1b, a0, a1, a2, a3);

        const u32* xb = sXu + (t & 1) * 256;
        const uint4 xv0 = *reinterpret_cast<const uint4*>(xb + R0 * XSu + tg * 4);
        const uint4 xv1 = *reinterpret_cast<const uint4*>(xb + R1 * XSu + tg * 4);
        u32 x0[2], x1[2], x2[2], x3[2];
        x0[0]=xv0.x; x2[0]=xv0.y; x0[1]=xv0.z; x2[1]=xv0.w;
        x1[0]=xv1.x; x3[0]=xv1.y; x1[1]=xv1.z; x3[1]=xv1.w;

        float accW[3][4], accP[4];
#pragma unroll
        for (int j = 0; j < 4; j++) {
            const int c = j & 1;
            accW[0][j] = ebr[c];
            accW[1][j] = ebz[c];
            accW[2][j] = enh[c];
            accP[j]    = eni[c];
        }
#pragma unroll
        for (int nt = 0; nt < 3; nt++) {
            float* A = accW[nt];
#pragma unroll
            for (int ks = 0; ks < 4; ks++)
                MMA(A, a0[ks], a1[ks], a2[ks], a3[ks], bh[nt][ks][0], bh[nt][ks][1]);
#pragma unroll
            for (int ks = 0; ks < 4; ks++) {
                const uint2 wl = sWl[((wn * 3 + nt) * 4 + ks) * 32 + lane];
                MMA(A, a0[ks], a1[ks], a2[ks], a3[ks], wl.x, wl.y);
            }
            float* T = (nt < 2) ? A : accP;
#pragma unroll
            for (int ks = 0; ks < 2; ks++) {
                const uint2 w = sWf[((wn * 3 + nt) * 2 + ks) * 32 + lane];
                MMA(T, x0[ks], x1[ks], x2[ks], x3[ks], w.x, w.y);
            }
        }

        u32* hwu = sHu + (hp ^ 1) * (16 * HSu);
#pragma unroll
        for (int rh = 0; rh < 2; rh++) {
#pragma unroll
            for (int c = 0; c < 2; c++) {
                const int j = 2 * rh + c;
                const float rg = fsig(accW[0][j]);
                const float zg = fsig(accW[1][j]);
                const float nn = tanhap(fmaf(rg, accW[2][j], accP[j]));
                h[j] = nn + zg * (h[j] - nn);
            }
            const int row = rh ? R1 : R0;
            hwu[row * HSu + tg * 8 + wn] = packh2(h[2 * rh], h[2 * rh + 1]);
        }
        hp ^= 1;
    }

    // ======================= decoder: 24 steps =======================
    __syncthreads();
#pragma unroll
    for (int nt = 0; nt < 3; nt++)   // restage decoder Wih
#pragma unroll
        for (int ks = 0; ks < 2; ks++) {
            const float* wr = dWih + (nt * 64 + 8 * wn + g) * 32 + ks * 16 + 2 * tg;
            sWf[((wn * 3 + nt) * 2 + ks) * 32 + lane] =
                make_uint2(packh2(wr[0], wr[1]), packh2(wr[8], wr[9]));
        }
    if (wn < 4) {                    // projection W frags (split hi/lo)
#pragma unroll
        for (int ks = 0; ks < 4; ks++) {
            const float* wr = pW + (8 * wn + g) * 64 + ks * 16 + 2 * tg;
            u32 h0, l0, h1, l1;
            splith2(wr[0], wr[1], h0, l0);
            splith2(wr[8], wr[9], h1, l1);
            sPf[(wn * 4 + ks) * 32 + lane] = make_uint4(h0, h1, l0, l1);
        }
    }
#pragma unroll
    for (int nt = 0; nt < 3; nt++) {   // decoder Whh frags (hi regs, lo smem)
        const float* row = dWhh + (nt * 64 + 8 * wn + g) * 64;
#pragma unroll
        for (int ks = 0; ks < 4; ks++) {
            const int k0 = ks * 16 + 2 * tg;
            u32 h0, l0, h1, l1;
            splith2(row[k0],     row[k0 + 1], h0, l0);
            splith2(row[k0 + 8], row[k0 + 9], h1, l1);
            bh[nt][ks][0] = h0; bh[nt][ks][1] = h1;
            sWl[((wn * 3 + nt) * 4 + ks) * 32 + lane] = make_uint2(l0, l1);
        }
    }
    float dbr[2], dbz[2], dni[2], dnh[2];
#pragma unroll
    for (int c = 0; c < 2; c++) {
        const int u = 8 * wn + 2 * tg + c;
        dbr[c] = dBih[u] + dBhh[u];
        dbz[c] = dBih[64 + u] + dBhh[64 + u];
        dni[c] = dBih[128 + u];
        dnh[c] = dBhh[128 + u];
    }
    const int pcol = 8 * wn + 2 * tg;           // valid for wn<4
    const float pb0 = (wn < 4) ? pB[pcol] : 0.f;
    const float pb1 = (wn < 4) ? pB[pcol + 1] : 0.f;

    {   // prev_0 = x[:, TIN-1, :] — copy permuted records (one u32 per thread)
        const int row = tid >> 4, w = tid & 15;
        sPu[row * PSu + w] = g_xs[((size_t)(TIN - 1) * B_ + rowbase + row) * 16 + w];
    }
    __syncthreads();

    int pp = 0;
    for (int t = 0; t < TOUT; t++) {
        const u32* hbu = sHu + hp * (16 * HSu);
        const uint4* h0p = reinterpret_cast<const uint4*>(hbu + R0 * HSu + tg * 8);
        const uint4* h1p = reinterpret_cast<const uint4*>(hbu + R1 * HSu + tg * 8);
        const uint4 v0a = h0p[0], v0b = h0p[1], v1a = h1p[0], v1b = h1p[1];
        u32 a0[4], a1[4], a2[4], a3[4];
        AFRAG_FROM(v0a, v0b, v1a, v1b, a0, a1, a2, a3);

        const u32* pbu = sPu + pp * (16 * PSu);
        const uint4 pv0 = *reinterpret_cast<const uint4*>(pbu + R0 * PSu + tg * 4);
        const uint4 pv1 = *reinterpret_cast<const uint4*>(pbu + R1 * PSu + tg * 4);
        u32 x0[2], x1[2], x2[2], x3[2];
        x0[0]=pv0.x; x2[0]=pv0.y; x0[1]=pv0.z; x2[1]=pv0.w;
        x1[0]=pv1.x; x3[0]=pv1.y; x1[1]=pv1.z; x3[1]=pv1.w;

        float accW[3][4], accP[4];
#pragma unroll
        for (int j = 0; j < 4; j++) {
            const int c = j & 1;
            accW[0][j] = dbr[c];
            accW[1][j] = dbz[c];
            accW[2][j] = dnh[c];
            accP[j]    = dni[c];
        }
#pragma unroll
        for (int nt = 0; nt < 3; nt++) {
            float* A = accW[nt];
#pragma unroll
            for (int ks = 0; ks < 4; ks++)
                MMA(A, a0[ks], a1[ks], a2[ks], a3[ks], bh[nt][ks][0], bh[nt][ks][1]);
#pragma unroll
            for (int ks = 0; ks < 4; ks++) {
                const uint2 wl = sWl[((wn * 3 + nt) * 4 + ks) * 32 + lane];
                MMA(A, a0[ks], a1[ks], a2[ks], a3[ks], wl.x, wl.y);
            }
            float* T = (nt < 2) ? A : accP;
#pragma unroll
            for (int ks = 0; ks < 2; ks++) {
                const uint2 w = sWf[((wn * 3 + nt) * 2 + ks) * 32 + lane];
                MMA(T, x0[ks], x1[ks], x2[ks], x3[ks], w.x, w.y);
            }
        }

        u32* hwu = sHu + (hp ^ 1) * (16 * HSu);
#pragma unroll
        for (int rh = 0; rh < 2; rh++) {
#pragma unroll
            for (int c = 0; c < 2; c++) {
                const int j = 2 * rh + c;
                const float rg = fsig(accW[0][j]);
                const float zg = fsig(accW[1][j]);
                const float nn = tanhap(fmaf(rg, accW[2][j], accP[j]));
                h[j] = nn + zg * (h[j] - nn);
            }
            const int row = rh ? R1 : R0;
            hwu[row * HSu + tg * 8 + wn] = packh2(h[2 * rh], h[2 * rh + 1]);
        }
        __syncthreads();

        // projection from NEW h (warps wn<4 -> output cols 8wn..8wn+7)
        if (wn < 4) {
            const u32* hnu = sHu + (hp ^ 1) * (16 * HSu);
            const uint4* n0p = reinterpret_cast<const uint4*>(hnu + R0 * HSu + tg * 8);
            const uint4* n1p = reinterpret_cast<const uint4*>(hnu + R1 * HSu + tg * 8);
            const uint4 w0a = n0p[0], w0b = n0p[1], w1a = n1p[0], w1b = n1p[1];
            u32 n0[4], n1[4], n2[4], n3[4];
            AFRAG_FROM(w0a, w0b, w1a, w1b, n0, n1, n2, n3);
            float pacc[4] = {0.f, 0.f, 0.f, 0.f};
#pragma unroll
            for (int ks = 0; ks < 4; ks++) {
                const uint4 w = sPf[(wn * 4 + ks) * 32 + lane];
                MMA(pacc, n0[ks], n1[ks], n2[ks], n3[ks], w.x, w.y);
                MMA(pacc, n0[ks], n1[ks], n2[ks], n3[ks], w.z, w.w);
            }
            const float p00 = pacc[0] + pb0, p01 = pacc[1] + pb1;
            const float p10 = pacc[2] + pb0, p11 = pacc[3] + pb1;
            *reinterpret_cast<float2*>(&out[((size_t)(rowbase + R0) * TOUT + t) * C_ + pcol]) = make_float2(p00, p01);
            *reinterpret_cast<float2*>(&out[((size_t)(rowbase + R1) * TOUT + t) * C_ + pcol]) = make_float2(p10, p11);
            u32* pnu = sPu + (pp ^ 1) * (16 * PSu);
            pnu[R0 * PSu + tg * 4 + wn] = packh2(p00, p01);
            pnu[R1 * PSu + tg * 4 + wn] = packh2(p10, p11);
        }
        __syncthreads();
        hp ^= 1; pp ^= 1;
    }
}

// ============================ launch ============================
extern "C" void kernel_launch(void* const* d_in, const int* in_sizes, int n_in,
                              void* d_out, int out_size)
{
    (void)in_sizes; (void)n_in; (void)out_size;
    const float* x    = (const float*)d_in[0];
    const float* eWih = (const float*)d_in[1];
    const float* eWhh = (const float*)d_in[2];
    const float* eBih = (const float*)d_in[3];
    const float* eBhh = (const float*)d_in[4];
    const float* dWih = (const float*)d_in[5];
    const float* dWhh = (const float*)d_in[6];
    const float* dBih = (const float*)d_in[7];
    const float* dBhh = (const float*)d_in[8];
    const float* pW   = (const float*)d_in[9];
    const float* pB   = (const float*)d_in[10];
    float* out = (float*)d_out;

    xsplit_kernel<<<(TIN * B_) / 256, 256>>>(x);

    cudaFuncSetAttribute(gru_fused,
                         cudaFuncAttributeMaxDynamicSharedMemorySize, SM_TOTAL);
    gru_fused<<<B_ / 16, 256, SM_TOTAL>>>(
        x, eWih, eWhh, eBih, eBhh, dWih, dWhh, dBih, dBhh, pW, pB, out);
}

// round 17
// speedup vs baseline: 1.3283x; 1.3283x over previous
#include <cuda_runtime.h>
#include <cuda_fp16.h>
#include <cstdint>

// GRU seq2seq forecaster — fused tensor-core recurrence (R12 structure,
// single-product fp16 Whh: h is already fp16-rounded, so the Whh-lo
// correction term is dropped -> 36 MMA/warp/step instead of 60).
//  K0: xsplit — x -> fp16 PERMUTED 64B records (frag-major u32 layout).
//  K1: 256 thr, 8 warps = 2 row-groups x 4 unit-quads, 32 rows/CTA, grid 128.

#define B_    4096
#define TIN   168
#define C_    32
#define H_    64
#define TOUT  24

typedef uint32_t u32;
typedef unsigned long long u64;

__device__ u32 g_xs[(size_t)TIN * B_ * 16];   // 44 MB fp16 permuted x records

__device__ __forceinline__ float tanhap(float a) {
    float r; asm("tanh.approx.f32 %0, %1;" : "=f"(r) : "f"(a)); return r;
}
__device__ __forceinline__ float fsig(float a) {           // sigma(a)=0.5+0.5*tanh(a/2)
    return fmaf(tanhap(0.5f * a), 0.5f, 0.5f);
}
__device__ __forceinline__ u32 packh2(float a, float b) {  // low fp16 = a, high = b
    u32 d; asm("cvt.rn.f16x2.f32 %0, %1, %2;" : "=r"(d) : "f"(b), "f"(a)); return d;
}
__device__ __forceinline__ void splith2(float a, float b, u32& hi2, u32& lo2) {
    hi2 = packh2(a, b);
    __half2 hv = *reinterpret_cast<const __half2*>(&hi2);
    lo2 = packh2(a - __low2float(hv), b - __high2float(hv));
}
__device__ __forceinline__ void MMA(float acc[4], u32 a0, u32 a1, u32 a2, u32 a3,
                                    u32 b0, u32 b1) {
    asm volatile(
        "mma.sync.aligned.m16n8k16.row.col.f32.f16.f16.f32 "
        "{%0,%1,%2,%3}, {%4,%5,%6,%7}, {%8,%9}, {%0,%1,%2,%3};"
        : "+f"(acc[0]), "+f"(acc[1]), "+f"(acc[2]), "+f"(acc[3])
        : "r"(a0), "r"(a1), "r"(a2), "r"(a3), "r"(b0), "r"(b1));
}
__device__ __forceinline__ u32 smem_u32(const void* p) {
    u32 a;
    asm("{ .reg .u64 t; cvta.to.shared.u64 t, %1; cvt.u32.u64 %0, t; }" : "=r"(a) : "l"(p));
    return a;
}
__device__ __forceinline__ void cp16(u32 daddr, const void* gsrc) {
    asm volatile("cp.async.cg.shared.global [%0], [%1], 16;"
                 :: "r"(daddr), "l"(gsrc) : "memory");
}

// ============================ kernel 0: x pre-split (fp16, permuted) ============================
__global__ __launch_bounds__(256)
void xsplit_kernel(const float* __restrict__ x)
{
    const int p = blockIdx.x * 256 + threadIdx.x;      // t*B + b
    const int t = p >> 12, b = p & (B_ - 1);
    const float4* s4 = reinterpret_cast<const float4*>(x + ((size_t)b * TIN + t) * C_);
    float4 v[8];
#pragma unroll
    for (int i = 0; i < 8; i++) v[i] = s4[i];
    u32 s[16];
#pragma unroll
    for (int i = 0; i < 8; i++) {
        s[2 * i]     = packh2(v[i].x, v[i].y);
        s[2 * i + 1] = packh2(v[i].z, v[i].w);
    }
    uint4* dst = reinterpret_cast<uint4*>(g_xs + (size_t)p * 16);
#pragma unroll
    for (int j4 = 0; j4 < 4; j4++)
        dst[j4] = make_uint4(s[j4], s[4 + j4], s[8 + j4], s[12 + j4]);
}

// ============================ kernel 1: fused recurrence ============================
#define HSu 36     // sH row stride (u32): 32 data + 4 pad
#define PSu 16
#define XSu 16

#define OFF_H   0                         // [2 par][32][HSu] u32 = 9216
#define OFF_P   9216                      // [2 par][32][PSu] u32 = 4096
#define OFF_X   13312                     // [2 grp][2 buf][16][XSu] u32 = 4096
#define OFF_WF  17408                     // [4 wq][6 nt][2 ks][32] uint2 = 12288
#define OFF_PF  29696                     // [4 wq][4 ks][32] uint4 = 8192
#define SM_TOTAL 37888

__device__ __forceinline__ int permrow(int ln, int wq) {
    return (ln >> 4) * 64 + 16 * wq + (ln & 15);
}
#define AFRAG_FROM(v0a, v0b, v1a, v1b, a0, a1, a2, a3)                     \
    a0[0]=(v0a).x; a2[0]=(v0a).y; a1[0]=(v1a).x; a3[0]=(v1a).y;            \
    a0[1]=(v0a).z; a2[1]=(v0a).w; a1[1]=(v1a).z; a3[1]=(v1a).w;            \
    a0[2]=(v0b).x; a2[2]=(v0b).y; a1[2]=(v1b).x; a3[2]=(v1b).y;            \
    a0[3]=(v0b).z; a2[3]=(v0b).w; a1[3]=(v1b).z; a3[3]=(v1b).w;

__global__ __launch_bounds__(256)
void gru_fused(const float* __restrict__ x,
               const float* __restrict__ eWih, const float* __restrict__ eWhh,
               const float* __restrict__ eBih, const float* __restrict__ eBhh,
               const float* __restrict__ dWih, const float* __restrict__ dWhh,
               const float* __restrict__ dBih, const float* __restrict__ dBhh,
               const float* __restrict__ pW,   const float* __restrict__ pB,
               float* __restrict__ out)
{
    extern __shared__ __align__(16) char smem[];
    u32* sHu       = reinterpret_cast<u32*>(smem + OFF_H);
    u32* sPu       = reinterpret_cast<u32*>(smem + OFF_P);
    const u32* sXu = reinterpret_cast<const u32*>(smem + OFF_X);
    uint2* sWf     = reinterpret_cast<uint2*>(smem + OFF_WF);
    uint4* sPf     = reinterpret_cast<uint4*>(smem + OFF_PF);
    const u32 smb = smem_u32(smem);

    const int tid  = threadIdx.x;
    const int wid  = tid >> 5;
    const int lane = tid & 31;
    const int g  = lane >> 2;
    const int tg = lane & 3;
    const int mh = wid >> 2;           // row-group (0,1)
    const int wq = wid & 3;            // unit quad
    const int R0 = mh * 16 + g, R1 = R0 + 8;
    const int lr0 = g, lr1 = g + 8;
    const int rowbase = blockIdx.x * 32;
    const int barid = 1 + mh;
    const int lt = tid & 127;

    for (int i = tid; i < 2 * 32 * HSu; i += 256) sHu[i] = 0;

    // ---- stage encoder Wih frags (hi fp16 only) ----
    if (mh == 0) {
#pragma unroll
        for (int nt = 0; nt < 6; nt++)
#pragma unroll
            for (int ks = 0; ks < 2; ks++) {
                const float* wr = eWih + permrow(nt * 8 + g, wq) * 32 + ks * 16 + 2 * tg;
                sWf[((wq * 6 + nt) * 2 + ks) * 32 + lane] =
                    make_uint2(packh2(wr[0], wr[1]), packh2(wr[8], wr[9]));
            }
    }
    // ---- encoder Whh frags: single fp16 product (no lo correction) ----
    u32 bh[6][4][2];
#pragma unroll
    for (int nt = 0; nt < 6; nt++) {
        const float* row = eWhh + permrow(nt * 8 + g, wq) * 64;
#pragma unroll
        for (int ks = 0; ks < 4; ks++) {
            const int k0 = ks * 16 + 2 * tg;
            bh[nt][ks][0] = packh2(row[k0],     row[k0 + 1]);
            bh[nt][ks][1] = packh2(row[k0 + 8], row[k0 + 9]);
        }
    }
    float ebr[4], ebz[4], eni[4], enh[4];
#pragma unroll
    for (int sp = 0; sp < 4; sp++) {
        const int u = 16 * wq + (sp >> 1) * 8 + 2 * tg + (sp & 1);
        ebr[sp] = eBih[u] + eBhh[u];
        ebz[sp] = eBih[64 + u] + eBhh[64 + u];
        eni[sp] = eBih[128 + u];
        enh[sp] = eBhh[128 + u];
    }
    __syncthreads();

    if (lt < 64) {   // prologue: prefetch own group's x tile t=0
        const int row = lt >> 2, ch = lt & 3;
        const char* src = reinterpret_cast<const char*>(
            g_xs + ((size_t)(rowbase + mh * 16 + row)) * 16) + ch * 16;
        cp16(smb + OFF_X + mh * 2048 + row * 64 + ch * 16, src);
        asm volatile("cp.async.commit_group;" ::: "memory");
    }

    float h[8];
#pragma unroll
    for (int e = 0; e < 8; e++) h[e] = 0.0f;
    int hp = 0;

    // ======================= encoder: 168 steps =======================
    for (int t = 0; t < TIN; t++) {
        asm volatile("cp.async.wait_group 0;" ::: "memory");
        asm volatile("bar.sync %0, %1;" :: "r"(barid), "r"(128) : "memory");
        if (t + 1 < TIN && lt < 64) {
            const int row = lt >> 2, ch = lt & 3;
            const char* src = reinterpret_cast<const char*>(
                g_xs + ((size_t)(t + 1) * B_ + rowbase + mh * 16 + row) * 16) + ch * 16;
            cp16(smb + OFF_X + mh * 2048 + ((t + 1) & 1) * 1024 + row * 64 + ch * 16, src);
            asm volatile("cp.async.commit_group;" ::: "memory");
        }

        const u32* hbu = sHu + hp * (32 * HSu);
        const uint4* h0p = reinterpret_cast<const uint4*>(hbu + R0 * HSu + tg * 8);
        const uint4* h1p = reinterpret_cast<const uint4*>(hbu + R1 * HSu + tg * 8);
        const uint4 v0a = h0p[0], v0b = h0p[1], v1a = h1p[0], v1b = h1p[1];
        u32 a0[4], a1[4], a2[4], a3[4];
        AFRAG_FROM(v0a, v0b, v1a, v1b, a0, a1, a2, a3);

        const u32* xb = sXu + mh * 512 + (t & 1) * 256;
        const uint4 xv0 = *reinterpret_cast<const uint4*>(xb + lr0 * XSu + tg * 4);
        const uint4 xv1 = *reinterpret_cast<const uint4*>(xb + lr1 * XSu + tg * 4);
        u32 x0[2], x1[2], x2[2], x3[2];
        x0[0]=xv0.x; x2[0]=xv0.y; x0[1]=xv0.z; x2[1]=xv0.w;
        x1[0]=xv1.x; x3[0]=xv1.y; x1[1]=xv1.z; x3[1]=xv1.w;

        float accW[6][4], accP[2][4];
#pragma unroll
        for (int s = 0; s < 2; s++)
#pragma unroll
            for (int j = 0; j < 4; j++) {
                const int c = s * 2 + (j & 1);
                accW[s][j]     = ebr[c];
                accW[2 + s][j] = ebz[c];
                accW[4 + s][j] = enh[c];
                accP[s][j]     = eni[c];
            }
#pragma unroll
        for (int nt = 0; nt < 6; nt++) {
            float* A = accW[nt];
#pragma unroll
            for (int ks = 0; ks < 4; ks++)
                MMA(A, a0[ks], a1[ks], a2[ks], a3[ks], bh[nt][ks][0], bh[nt][ks][1]);
            float* T = (nt < 4) ? A : accP[nt - 4];
#pragma unroll
            for (int ks = 0; ks < 2; ks++) {
                const uint2 w = sWf[((wq * 6 + nt) * 2 + ks) * 32 + lane];
                MMA(T, x0[ks], x1[ks], x2[ks], x3[ks], w.x, w.y);
            }
        }

        u32* hwu = sHu + (hp ^ 1) * (32 * HSu);
#pragma unroll
        for (int rh = 0; rh < 2; rh++) {
#pragma unroll
            for (int s = 0; s < 2; s++) {
                const int e = rh * 4 + s * 2;
                const float rg0 = fsig(accW[s][2*rh]);
                const float rg1 = fsig(accW[s][2*rh+1]);
                const float z0  = fsig(accW[2+s][2*rh]);
                const float z1  = fsig(accW[2+s][2*rh+1]);
                const float n0  = tanhap(fmaf(rg0, accW[4+s][2*rh],   accP[s][2*rh]));
                const float n1  = tanhap(fmaf(rg1, accW[4+s][2*rh+1], accP[s][2*rh+1]));
                h[e]   = n0 + z0 * (h[e]   - n0);
                h[e+1] = n1 + z1 * (h[e+1] - n1);
            }
        }
#pragma unroll
        for (int rh = 0; rh < 2; rh++) {
            const u32 p0 = packh2(h[rh*4+0], h[rh*4+1]);
            const u32 p1 = packh2(h[rh*4+2], h[rh*4+3]);
            const int row = rh ? R1 : R0;
            *reinterpret_cast<u64*>(&hwu[row * HSu + tg * 8 + 2 * wq]) =
                ((u64)p1 << 32) | p0;
        }
        hp ^= 1;
    }

    // ======================= decoder: 24 steps =======================
    __syncthreads();
    if (mh == 0) {
#pragma unroll
        for (int nt = 0; nt < 6; nt++)
#pragma unroll
            for (int ks = 0; ks < 2; ks++) {
                const float* wr = dWih + permrow(nt * 8 + g, wq) * 32 + ks * 16 + 2 * tg;
                sWf[((wq * 6 + nt) * 2 + ks) * 32 + lane] =
                    make_uint2(packh2(wr[0], wr[1]), packh2(wr[8], wr[9]));
            }
#pragma unroll
        for (int ks = 0; ks < 4; ks++) {
            const float* wr = pW + (8 * wq + g) * 64 + ks * 16 + 2 * tg;
            u32 h0, l0, h1, l1;
            splith2(wr[0], wr[1], h0, l0);
            splith2(wr[8], wr[9], h1, l1);
            sPf[(wq * 4 + ks) * 32 + lane] = make_uint4(h0, h1, l0, l1);
        }
    }
#pragma unroll
    for (int nt = 0; nt < 6; nt++) {
        const float* row = dWhh + permrow(nt * 8 + g, wq) * 64;
#pragma unroll
        for (int ks = 0; ks < 4; ks++) {
            const int k0 = ks * 16 + 2 * tg;
            bh[nt][ks][0] = packh2(row[k0],     row[k0 + 1]);
            bh[nt][ks][1] = packh2(row[k0 + 8], row[k0 + 9]);
        }
    }
    float dbr[4], dbz[4], dni[4], dnh[4];
#pragma unroll
    for (int sp = 0; sp < 4; sp++) {
        const int u = 16 * wq + (sp >> 1) * 8 + 2 * tg + (sp & 1);
        dbr[sp] = dBih[u] + dBhh[u];
        dbz[sp] = dBih[64 + u] + dBhh[64 + u];
        dni[sp] = dBih[128 + u];
        dnh[sp] = dBhh[128 + u];
    }
    const int pcol = 8 * wq + 2 * tg;
    const float pb0 = pB[pcol], pb1 = pB[pcol + 1];

    for (int i = lt; i < 16 * 16; i += 128) {
        const int row = i >> 4, w = i & 15;
        sPu[(mh * 16 + row) * PSu + w] =
            g_xs[((size_t)(TIN - 1) * B_ + rowbase + mh * 16 + row) * 16 + w];
    }
    __syncthreads();

    int pp = 0;
    for (int t = 0; t < TOUT; t++) {
        const u32* hbu = sHu + hp * (32 * HSu);
        const uint4* h0p = reinterpret_cast<const uint4*>(hbu + R0 * HSu + tg * 8);
        const uint4* h1p = reinterpret_cast<const uint4*>(hbu + R1 * HSu + tg * 8);
        const uint4 v0a = h0p[0], v0b = h0p[1], v1a = h1p[0], v1b = h1p[1];
        u32 a0[4], a1[4], a2[4], a3[4];
        AFRAG_FROM(v0a, v0b, v1a, v1b, a0, a1, a2, a3);

        const u32* pbu = sPu + pp * (32 * PSu);
        const uint4 pv0 = *reinterpret_cast<const uint4*>(pbu + R0 * PSu + tg * 4);
        const uint4 pv1 = *reinterpret_cast<const uint4*>(pbu + R1 * PSu + tg * 4);
        u32 x0[2], x1[2], x2[2], x3[2];
        x0[0]=pv0.x; x2[0]=pv0.y; x0[1]=pv0.z; x2[1]=pv0.w;
        x1[0]=pv1.x; x3[0]=pv1.y; x1[1]=pv1.z; x3[1]=pv1.w;

        float accW[6][4], accP[2][4];
#pragma unroll
        for (int s = 0; s < 2; s++)
#pragma unroll
            for (int j = 0; j < 4; j++) {
                const int c = s * 2 + (j & 1);
                accW[s][j]     = dbr[c];
                accW[2 + s][j] = dbz[c];
                accW[4 + s][j] = dnh[c];
                accP[s][j]     = dni[c];
            }
#pragma unroll
        for (int nt = 0; nt < 6; nt++) {
            float* A = accW[nt];
#pragma unroll
            for (int ks = 0; ks < 4; ks++)
                MMA(A, a0[ks], a1[ks], a2[ks], a3[ks], bh[nt][ks][0], bh[nt][ks][1]);
            float* T = (nt < 4) ? A : accP[nt - 4];
#pragma unroll
            for (int ks = 0; ks < 2; ks++) {
                const uint2 w = sWf[((wq * 6 + nt) * 2 + ks) * 32 + lane];
                MMA(T, x0[ks], x1[ks], x2[ks], x3[ks], w.x, w.y);
            }
        }

        u32* hwu = sHu + (hp ^ 1) * (32 * HSu);
#pragma unroll
        for (int rh = 0; rh < 2; rh++) {
#pragma unroll
            for (int s = 0; s < 2; s++) {
                const int e = rh * 4 + s * 2;
                const float rg0 = fsig(accW[s][2*rh]);
                const float rg1 = fsig(accW[s][2*rh+1]);
                const float z0  = fsig(accW[2+s][2*rh]);
                const float z1  = fsig(accW[2+s][2*rh+1]);
                const float n0  = tanhap(fmaf(rg0, accW[4+s][2*rh],   accP[s][2*rh]));
                const float n1  = tanhap(fmaf(rg1, accW[4+s][2*rh+1], accP[s][2*rh+1]));
                h[e]   = n0 + z0 * (h[e]   - n0);
                h[e+1] = n1 + z1 * (h[e+1] - n1);
            }
        }
#pragma unroll
        for (int rh = 0; rh < 2; rh++) {
            const u32 p0 = packh2(h[rh*4+0], h[rh*4+1]);
            const u32 p1 = packh2(h[rh*4+2], h[rh*4+3]);
            const int row = rh ? R1 : R0;
            *reinterpret_cast<u64*>(&hwu[row * HSu + tg * 8 + 2 * wq]) =
                ((u64)p1 << 32) | p0;
        }
        asm volatile("bar.sync %0, %1;" :: "r"(barid), "r"(128) : "memory");

        // projection from NEW h
        {
            const u32* hnu = sHu + (hp ^ 1) * (32 * HSu);
            const uint4* n0p = reinterpret_cast<const uint4*>(hnu + R0 * HSu + tg * 8);
            const uint4* n1p = reinterpret_cast<const uint4*>(hnu + R1 * HSu + tg * 8);
            const uint4 w0a = n0p[0], w0b = n0p[1], w1a = n1p[0], w1b = n1p[1];
            u32 n0[4], n1[4], n2[4], n3[4];
            AFRAG_FROM(w0a, w0b, w1a, w1b, n0, n1, n2, n3);
            float pacc[4] = {0.f, 0.f, 0.f, 0.f};
#pragma unroll
            for (int ks = 0; ks < 4; ks++) {
                const uint4 w = sPf[(wq * 4 + ks) * 32 + lane];
                MMA(pacc, n0[ks], n1[ks], n2[ks], n3[ks], w.x, w.y);
                MMA(pacc, n0[ks], n1[ks], n2[ks], n3[ks], w.z, w.w);
            }
            const float p00 = pacc[0] + pb0, p01 = pacc[1] + pb1;
            const float p10 = pacc[2] + pb0, p11 = pacc[3] + pb1;
            *reinterpret_cast<float2*>(&out[((size_t)(rowbase + R0) * TOUT + t) * C_ + pcol]) = make_float2(p00, p01);
            *reinterpret_cast<float2*>(&out[((size_t)(rowbase + R1) * TOUT + t) * C_ + pcol]) = make_float2(p10, p11);
            u32* pnu = sPu + (pp ^ 1) * (32 * PSu);
            pnu[R0 * PSu + tg * 4 + wq] = packh2(p00, p01);
            pnu[R1 * PSu + tg * 4 + wq] = packh2(p10, p11);
        }
        asm volatile("bar.sync %0, %1;" :: "r"(barid), "r"(128) : "memory");
        hp ^= 1; pp ^= 1;
    }
}

// ============================ launch ============================
extern "C" void kernel_launch(void* const* d_in, const int* in_sizes, int n_in,
                              void* d_out, int out_size)
{
    (void)in_sizes; (void)n_in; (void)out_size;
    const float* x    = (const float*)d_in[0];
    const float* eWih = (const float*)d_in[1];
    const float* eWhh = (const float*)d_in[2];
    const float* eBih = (const float*)d_in[3];
    const float* eBhh = (const float*)d_in[4];
    const float* dWih = (const float*)d_in[5];
    const float* dWhh = (const float*)d_in[6];
    const float* dBih = (const float*)d_in[7];
    const float* dBhh = (const float*)d_in[8];
    const float* pW   = (const float*)d_in[9];
    const float* pB   = (const float*)d_in[10];
    float* out = (float*)d_out;

    xsplit_kernel<<<(TIN * B_) / 256, 256>>>(x);

    cudaFuncSetAttribute(gru_fused,
                         cudaFuncAttributeMaxDynamicSharedMemorySize, SM_TOTAL);
    gru_fused<<<B_ / 32, 256, SM_TOTAL>>>(
        x, eWih, eWhh, eBih, eBhh, dWih, dWhh, dBih, dBhh, pW, pB, out);
}